// round 13
// baseline (speedup 1.0000x reference)
#include <cuda_runtime.h>
#include <cstdint>

// DiagLinear, two-phase, stream-pipelined:
//   K1 diag_gemm (x4 m-chunks, capture stream): per-partition TF32 mma.sync
//      GEMM -> scratch ytmp[m][p][n] (contiguous stores; bias folded).
//   K2 permute_out (x4 chunks, forked stream): ytmp[m][p][n] -> y[m][n*16+p],
//      overlapped with the next GEMM chunk via event fork/join.

#define P_PART 16
#define DIN    256
#define DOUT   256
#define MROWS  16384
#define KC     32
#define NCHUNK 8
#define STAGES 3
#define MCHUNKS 4

#define ABUF_BYTES 16384
#define BBUF_BYTES 16384
#define SMEM_B_OFF (STAGES * ABUF_BYTES)                // 49152
#define SMEM_BIAS  (SMEM_B_OFF + STAGES * BBUF_BYTES)   // 98304
#define GEMM_SMEM  (SMEM_BIAS + 640)                    // 98944

#define NPAD 260

__device__ float g_wtf[(size_t)P_PART * DOUT * DIN];        // rna W, 4MB
__device__ float g_ytmp[(size_t)MROWS * P_PART * DOUT];     // [m][p][n], 256MB

static __device__ __forceinline__ uint32_t smem_u32(const void* p) {
    uint32_t a;
    asm("{ .reg .u64 t; cvta.to.shared.u64 t, %1; cvt.u32.u64 %0, t; }" : "=r"(a) : "l"(p));
    return a;
}

static __device__ __forceinline__ uint32_t f2tf32(float v) {
    uint32_t u;
    asm("cvt.rna.tf32.f32 %0, %1;" : "=r"(u) : "f"(v));
    return u;
}

static __device__ __forceinline__ void cp_async16(uint32_t dst, const void* src) {
    asm volatile("cp.async.cg.shared.global [%0], [%1], 16;" :: "r"(dst), "l"(src));
}

__global__ __launch_bounds__(256)
void round_w(const float* __restrict__ w)
{
    int i = blockIdx.x * 256 + threadIdx.x;
    float4 v = reinterpret_cast<const float4*>(w)[i];
    float4 r;
    r.x = __uint_as_float(f2tf32(v.x));
    r.y = __uint_as_float(f2tf32(v.y));
    r.z = __uint_as_float(f2tf32(v.z));
    r.w = __uint_as_float(f2tf32(v.w));
    reinterpret_cast<float4*>(g_wtf)[i] = r;
}

__global__ __launch_bounds__(256, 2)
void diag_gemm(const float* __restrict__ x, const float* __restrict__ bias,
               int mtile0)
{
    extern __shared__ char smem[];
    const int tid  = threadIdx.x;
    const int wid  = tid >> 5;
    const int lane = tid & 31;

    const int p     = blockIdx.x & 15;
    const int nhalf = blockIdx.x >> 4;
    const int n0    = nhalf * 128;
    const int m0    = (mtile0 + blockIdx.y) * 128;

    const int warp_m = wid & 3;
    const int warp_n = wid >> 2;

    const float* xbase = x + (size_t)m0 * (P_PART * DIN) + (size_t)p * DIN;
    const float* wbase = g_wtf + (size_t)p * (DOUT * DIN) + (size_t)n0 * DIN;

    const uint32_t sbase = smem_u32(smem);

    {   // bias_s[i] = bias[(n0+i)*16 + p]
        float* bias_s = reinterpret_cast<float*>(smem + SMEM_BIAS);
        if (tid < 128) bias_s[tid] = bias[(n0 + tid) * P_PART + p];
    }

    const int g  = lane >> 3;
    const int l8 = lane & 7;
    const int rowA = warp_m * 32 + (g & 1) * 8 + l8;
    const int cA   = g >> 1;
    const int rowB = warp_n * 64 + (g >> 1) * 8 + l8;
    const int cB   = g & 1;

    const uint32_t aAddr0 = sbase + rowA * 128;
    const uint32_t bAddr0 = sbase + SMEM_B_OFF + rowB * 128;
    const int swA = rowA & 7, swB = rowB & 7;

#define ISSUE_STAGE(KCI, ST)                                                    \
    {                                                                           \
        const int kofs = (KCI) * KC;                                            \
        _Pragma("unroll")                                                       \
        for (int i = 0; i < 4; i++) {                                           \
            int idx = i * 256 + tid;                                            \
            int row = idx >> 3, q = idx & 7;                                    \
            uint32_t so = row * 128 + ((q ^ (row & 7)) << 4);                   \
            cp_async16(sbase + (ST) * ABUF_BYTES + so,                          \
                       xbase + (size_t)row * (P_PART * DIN) + kofs + q * 4);    \
            cp_async16(sbase + SMEM_B_OFF + (ST) * BBUF_BYTES + so,             \
                       wbase + (size_t)row * DIN + kofs + q * 4);               \
        }                                                                       \
        asm volatile("cp.async.commit_group;" ::: "memory");                    \
    }

    float acc[2][8][4];
#pragma unroll
    for (int mm = 0; mm < 2; mm++)
#pragma unroll
        for (int nn = 0; nn < 8; nn++)
#pragma unroll
            for (int c = 0; c < 4; c++) acc[mm][nn][c] = 0.0f;

#define LD_FRAGS(SET, ABASE, BBASE, KS)                                         \
    {                                                                           \
        const int cb = (KS) * 2;                                                \
        _Pragma("unroll")                                                       \
        for (int mm = 0; mm < 2; mm++) {                                        \
            uint32_t ad = (ABASE) + mm * 2048 + (((cb + cA) ^ swA) << 4);       \
            asm volatile(                                                       \
                "ldmatrix.sync.aligned.m8n8.x4.shared.b16 {%0,%1,%2,%3}, [%4];" \
                : "=r"(a[SET][mm][0]), "=r"(a[SET][mm][1]),                     \
                  "=r"(a[SET][mm][2]), "=r"(a[SET][mm][3])                      \
                : "r"(ad));                                                     \
        }                                                                       \
        _Pragma("unroll")                                                       \
        for (int q = 0; q < 4; q++) {                                           \
            uint32_t bd = (BBASE) + q * 2048 + (((cb + cB) ^ swB) << 4);        \
            asm volatile(                                                       \
                "ldmatrix.sync.aligned.m8n8.x4.shared.b16 {%0,%1,%2,%3}, [%4];" \
                : "=r"(b[SET][q][0]), "=r"(b[SET][q][1]),                       \
                  "=r"(b[SET][q][2]), "=r"(b[SET][q][3])                        \
                : "r"(bd));                                                     \
        }                                                                       \
    }

#define MMA_SET(SET)                                                            \
    _Pragma("unroll")                                                           \
    for (int mm = 0; mm < 2; mm++)                                              \
        _Pragma("unroll")                                                       \
        for (int nn = 0; nn < 8; nn++) {                                        \
            asm volatile(                                                       \
                "mma.sync.aligned.m16n8k8.row.col.f32.tf32.tf32.f32 "           \
                "{%0,%1,%2,%3}, {%4,%5,%6,%7}, {%8,%9}, {%0,%1,%2,%3};"         \
                : "+f"(acc[mm][nn][0]), "+f"(acc[mm][nn][1]),                   \
                  "+f"(acc[mm][nn][2]), "+f"(acc[mm][nn][3])                    \
                : "r"(a[SET][mm][0]), "r"(a[SET][mm][1]),                       \
                  "r"(a[SET][mm][2]), "r"(a[SET][mm][3]),                       \
                  "r"(b[SET][nn >> 1][(nn & 1) * 2]),                           \
                  "r"(b[SET][nn >> 1][(nn & 1) * 2 + 1]));                      \
        }

#define COMPUTE(BUF)                                                            \
    {                                                                           \
        const uint32_t abase = aAddr0 + (BUF) * ABUF_BYTES;                     \
        const uint32_t bbase = bAddr0 + (BUF) * BBUF_BYTES;                     \
        uint32_t a[2][2][4], b[2][4][4];                                        \
        LD_FRAGS(0, abase, bbase, 0);                                           \
        LD_FRAGS(1, abase, bbase, 1);                                           \
        MMA_SET(0);                                                             \
        LD_FRAGS(0, abase, bbase, 2);                                           \
        MMA_SET(1);                                                             \
        LD_FRAGS(1, abase, bbase, 3);                                           \
        MMA_SET(0);                                                             \
        MMA_SET(1);                                                             \
    }

    ISSUE_STAGE(0, 0);
    ISSUE_STAGE(1, 1);

#pragma unroll 1
    for (int kc = 0; kc < NCHUNK; kc++) {
        asm volatile("cp.async.wait_group 1;" ::: "memory");
        __syncthreads();
        if (kc + 2 < NCHUNK) {
            const int st = (kc + 2) % 3;
            ISSUE_STAGE(kc + 2, st);
        }
        COMPUTE(kc % 3);
    }

    // ---- epilogue: contiguous stores to ytmp[m][p][n] (+bias) ----
    {
        const float* bias_s = reinterpret_cast<const float*>(smem + SMEM_BIAS);
        const int r0 = lane >> 2;
        const int c0 = (lane & 3) * 2;
#pragma unroll
        for (int mm = 0; mm < 2; mm++) {
            const int mr = m0 + warp_m * 32 + mm * 16 + r0;
            float* yt0 = g_ytmp + ((size_t)mr * P_PART + p) * DOUT + n0;
            float* yt1 = yt0 + (size_t)8 * P_PART * DOUT;
#pragma unroll
            for (int nn = 0; nn < 8; nn++) {
                const int nl = warp_n * 64 + nn * 8 + c0;
                const float b0 = bias_s[nl], b1 = bias_s[nl + 1];
                *reinterpret_cast<float2*>(yt0 + nl) =
                    make_float2(acc[mm][nn][0] + b0, acc[mm][nn][1] + b1);
                *reinterpret_cast<float2*>(yt1 + nl) =
                    make_float2(acc[mm][nn][2] + b0, acc[mm][nn][3] + b1);
            }
        }
    }
}

// ---- K2: permute ytmp[m][p][n] -> y[m][n*16+p] ----
__global__ __launch_bounds__(256)
void permute_out(float* __restrict__ y, int mb0)
{
    __shared__ float ts[2][P_PART * NPAD];
    const int tid = threadIdx.x;
    const int mb  = mb0 + blockIdx.x * 2;

    const float* src = g_ytmp + (size_t)mb * (P_PART * DOUT);
#pragma unroll
    for (int m = 0; m < 2; m++) {
#pragma unroll
        for (int i = 0; i < 4; i++) {
            int idx = i * 256 + tid;            // float4 index 0..1023
            int pp  = idx >> 6;
            int n4  = idx & 63;
            float4 v = *reinterpret_cast<const float4*>(
                src + (size_t)m * (P_PART * DOUT) + pp * DOUT + n4 * 4);
            *reinterpret_cast<float4*>(&ts[m][pp * NPAD + n4 * 4]) = v;
        }
    }
    __syncthreads();

#pragma unroll
    for (int m = 0; m < 2; m++) {
        float* yrow = y + (size_t)(mb + m) * (DOUT * P_PART);
#pragma unroll
        for (int i = 0; i < 4; i++) {
            int o  = (i * 256 + tid) * 4;
            int pb = o & 15;
            int n  = o >> 4;
            float4 r;
            r.x = ts[m][(pb + 0) * NPAD + n];
            r.y = ts[m][(pb + 1) * NPAD + n];
            r.z = ts[m][(pb + 2) * NPAD + n];
            r.w = ts[m][(pb + 3) * NPAD + n];
            *reinterpret_cast<float4*>(yrow + o) = r;
        }
    }
}

extern "C" void kernel_launch(void* const* d_in, const int* in_sizes, int n_in,
                              void* d_out, int out_size)
{
    const float* x    = (const float*)d_in[0];
    const float* w    = (const float*)d_in[1];
    const float* bias = (const float*)d_in[2];
    float* y = (float*)d_out;

    int M = in_sizes[0] / (P_PART * DIN);      // 16384
    const int mtiles       = M / 128;          // 128
    const int mtiles_chunk = mtiles / MCHUNKS; // 32
    const int prows_chunk  = (M / 2) / MCHUNKS;// 2048

    // One-time setup on the (uncaptured) correctness call.
    static cudaStream_t s2 = nullptr;
    static cudaEvent_t evFork[MCHUNKS];
    static cudaEvent_t evJoin;
    if (s2 == nullptr) {
        cudaStreamCreateWithFlags(&s2, cudaStreamNonBlocking);
        for (int c = 0; c < MCHUNKS; c++)
            cudaEventCreateWithFlags(&evFork[c], cudaEventDisableTiming);
        cudaEventCreateWithFlags(&evJoin, cudaEventDisableTiming);
        cudaFuncSetAttribute(diag_gemm,
                             cudaFuncAttributeMaxDynamicSharedMemorySize, GEMM_SMEM);
    }

    round_w<<<(P_PART * DOUT * DIN) / 1024, 256>>>(w);

    for (int c = 0; c < MCHUNKS; c++) {
        diag_gemm<<<dim3(32, mtiles_chunk), 256, GEMM_SMEM>>>(x, bias, c * mtiles_chunk);
        cudaEventRecord(evFork[c], 0);
        cudaStreamWaitEvent(s2, evFork[c], 0);
        permute_out<<<prows_chunk, 256, 0, s2>>>(y, c * prows_chunk * 2);
    }

    // Join the forked stream back before returning.
    cudaEventRecord(evJoin, s2);
    cudaStreamWaitEvent(0, evJoin, 0);
}